// round 16
// baseline (speedup 1.0000x reference)
#include <cuda_runtime.h>
#include <cuda_fp16.h>
#include <cstdint>

// Dataset: N=50000 nodes, E=1250000 edges, D=64.
#define D_FEAT   64
#define NMAX     65536
#define SLOTS    96            // bucket capacity per node (Poisson(25): P(>96)~1e-30)
#define OVF_CAP  65536

// g_cnt[0..N-1] = per-node edge count; g_cnt[N] = overflow counter.
__device__ int    g_cnt[NMAX + 1];
__device__ int2   g_slot[(size_t)NMAX * SLOTS];    // (src, eid) buckets, stride 96
__device__ int3   g_ovf[OVF_CAP];                  // (src, eid, dst) overflow edges
__device__ __half g_xh[(size_t)NMAX * D_FEAT];     // fp16 shadow of x (halves gather traffic)

__device__ __forceinline__ int load_idx(const void* idx, long long i, int is64) {
    if (is64) return (int)((const long long*)idx)[i];
    return ((const int*)idx)[i];
}

// Per-block dtype detection (int32 misread as int64 lands in [0,N) w.p. ~2e-5/sample)
__device__ __forceinline__ int detect_is64(const void* idx, int E, int N) {
    __shared__ int s_is64;
    if (threadIdx.x < 32) {
        int step = E / 32 > 0 ? E / 32 : 1;
        long long v = ((const long long*)idx)[(long long)threadIdx.x * step];
        bool okv = (v >= 0 && v < (long long)N);
        unsigned m = __ballot_sync(0xFFFFFFFFu, okv);
        if (threadIdx.x == 0) s_is64 = (m == 0xFFFFFFFFu) ? 1 : 0;
    }
    __syncthreads();
    return s_is64;
}

// 256-bit loads with L2 eviction priority (sm_103: evict hints need .v8.b32).
__device__ __forceinline__ void ldg_el8(const float* p, float* o) {
    unsigned r0, r1, r2, r3, r4, r5, r6, r7;
    asm volatile("ld.global.nc.L2::evict_last.v8.b32 {%0,%1,%2,%3,%4,%5,%6,%7}, [%8];"
                 : "=r"(r0), "=r"(r1), "=r"(r2), "=r"(r3),
                   "=r"(r4), "=r"(r5), "=r"(r6), "=r"(r7) : "l"(p));
    o[0] = __uint_as_float(r0); o[1] = __uint_as_float(r1);
    o[2] = __uint_as_float(r2); o[3] = __uint_as_float(r3);
    o[4] = __uint_as_float(r4); o[5] = __uint_as_float(r5);
    o[6] = __uint_as_float(r6); o[7] = __uint_as_float(r7);
}
__device__ __forceinline__ void ldg_ef8(const float* p, float* o) {
    unsigned r0, r1, r2, r3, r4, r5, r6, r7;
    asm volatile("ld.global.nc.L2::evict_first.v8.b32 {%0,%1,%2,%3,%4,%5,%6,%7}, [%8];"
                 : "=r"(r0), "=r"(r1), "=r"(r2), "=r"(r3),
                   "=r"(r4), "=r"(r5), "=r"(r6), "=r"(r7) : "l"(p));
    o[0] = __uint_as_float(r0); o[1] = __uint_as_float(r1);
    o[2] = __uint_as_float(r2); o[3] = __uint_as_float(r3);
    o[4] = __uint_as_float(r4); o[5] = __uint_as_float(r5);
    o[6] = __uint_as_float(r6); o[7] = __uint_as_float(r7);
}
// fp16 gather load: 16B = 8 halves -> 8 floats.
__device__ __forceinline__ void ldg_xh8(const __half* p, float* o) {
    uint4 h = __ldg(reinterpret_cast<const uint4*>(p));
    float2 f;
    f = __half22float2(*reinterpret_cast<__half2*>(&h.x)); o[0] = f.x; o[1] = f.y;
    f = __half22float2(*reinterpret_cast<__half2*>(&h.y)); o[2] = f.x; o[3] = f.y;
    f = __half22float2(*reinterpret_cast<__half2*>(&h.z)); o[4] = f.x; o[5] = f.y;
    f = __half22float2(*reinterpret_cast<__half2*>(&h.w)); o[6] = f.x; o[7] = f.y;
}

// ---------------------------------------------------------------------------
// K0: dense x -> fp16 shadow (one pass, ~2.5us). Only the SUM term uses fp16;
// the deg*x[n] diagonal term stays fp32-exact in agg.
// ---------------------------------------------------------------------------
__global__ void cvt_kernel(const float* __restrict__ x, int n8) {
    int i = blockIdx.x * blockDim.x + threadIdx.x;   // one thread = 8 floats
    if (i >= n8) return;
    const float4* p = reinterpret_cast<const float4*>(x + (size_t)i * 8);
    float4 a = __ldg(p), b = __ldg(p + 1);
    __half2 h0 = __floats2half2_rn(a.x, a.y);
    __half2 h1 = __floats2half2_rn(a.z, a.w);
    __half2 h2 = __floats2half2_rn(b.x, b.y);
    __half2 h3 = __floats2half2_rn(b.z, b.w);
    uint4 o;
    o.x = *reinterpret_cast<unsigned*>(&h0);
    o.y = *reinterpret_cast<unsigned*>(&h1);
    o.z = *reinterpret_cast<unsigned*>(&h2);
    o.w = *reinterpret_cast<unsigned*>(&h3);
    *reinterpret_cast<uint4*>(g_xh + (size_t)i * 8) = o;
}

// ---------------------------------------------------------------------------
// K1: scatter — 4 edges/thread, vectorized index loads. At the LSU/LTS
// transaction floor (~25us, invariant across all variants tried).
// ---------------------------------------------------------------------------
__global__ void scatter_kernel(const void* __restrict__ idx, int E, int N) {
    int is64 = detect_is64(idx, E, N);
    int base = (blockIdx.x * blockDim.x + threadIdx.x) * 4;
    if (base >= E) return;
    int s[4], d[4];

    if (base + 4 <= E) {
        if (is64) {
            const longlong2* ps = reinterpret_cast<const longlong2*>(
                (const long long*)idx + base);
            const longlong2* pd = reinterpret_cast<const longlong2*>(
                (const long long*)idx + E + base);
            longlong2 s01 = __ldg(ps), s23 = __ldg(ps + 1);
            longlong2 d01 = __ldg(pd), d23 = __ldg(pd + 1);
            s[0] = (int)s01.x; s[1] = (int)s01.y; s[2] = (int)s23.x; s[3] = (int)s23.y;
            d[0] = (int)d01.x; d[1] = (int)d01.y; d[2] = (int)d23.x; d[3] = (int)d23.y;
        } else {
            int4 sv = __ldg(reinterpret_cast<const int4*>((const int*)idx + base));
            int4 dv = __ldg(reinterpret_cast<const int4*>((const int*)idx + E + base));
            s[0] = sv.x; s[1] = sv.y; s[2] = sv.z; s[3] = sv.w;
            d[0] = dv.x; d[1] = dv.y; d[2] = dv.z; d[3] = dv.w;
        }
    } else {
        #pragma unroll
        for (int k = 0; k < 4; ++k) {
            if (base + k < E) {
                s[k] = load_idx(idx, base + k, is64);
                d[k] = load_idx(idx, (long long)E + base + k, is64);
            } else { s[k] = -1; d[k] = -1; }
        }
    }

    #pragma unroll
    for (int k = 0; k < 4; ++k) {
        if ((unsigned)s[k] < (unsigned)N && (unsigned)d[k] < (unsigned)N) {
            int pos = atomicAdd(&g_cnt[d[k]], 1);
            if (pos < SLOTS) {
                g_slot[(size_t)d[k] * SLOTS + pos] = make_int2(s[k], base + k);
            } else {
                int o = atomicAdd(&g_cnt[N], 1);     // overflow counter
                if (o < OVF_CAP) g_ovf[o] = make_int3(s[k], base + k, d[k]);
            }
        }
    }
}

// ---------------------------------------------------------------------------
// K2: aggregation — static one node per 8-lane group, T=128. x[src] gathered
// from the fp16 shadow (halves the dominant L2 gather traffic); ea streamed
// fp32 evict_first; diagonal deg*x[n] term fp32-exact; out stored streaming.
// out[n] = deg(n)*x[n] + sum_{e: dst=n} (x[src_e] + ea[e])
// ---------------------------------------------------------------------------
__global__ void __launch_bounds__(128) agg_kernel(const float* __restrict__ x,
                                                  const float* __restrict__ ea,
                                                  float* __restrict__ out, int N) {
    int t = blockIdx.x * blockDim.x + threadIdx.x;
    int node = t >> 3;               // one node per 8-lane group
    if (node >= N) return;
    int c = (t & 7) << 3;            // float column offset: 0,8,...,56

    int deg = g_cnt[node];
    int m = deg < SLOTS ? deg : SLOTS;
    const int2* __restrict__ sp = g_slot + (size_t)node * SLOTS;

    float acc[8] = {0.f, 0.f, 0.f, 0.f, 0.f, 0.f, 0.f, 0.f};
    int j = 0;
    for (; j + 1 < m; j += 2) {
        int2 p0 = __ldg(&sp[j]);
        int2 p1 = __ldg(&sp[j + 1]);
        float xs0[8], av0[8], xs1[8], av1[8];
        ldg_xh8(g_xh + (size_t)p0.x * D_FEAT + c, xs0);
        ldg_ef8(ea   + (size_t)p0.y * D_FEAT + c, av0);
        ldg_xh8(g_xh + (size_t)p1.x * D_FEAT + c, xs1);
        ldg_ef8(ea   + (size_t)p1.y * D_FEAT + c, av1);
        #pragma unroll
        for (int k = 0; k < 8; ++k)
            acc[k] += (xs0[k] + av0[k]) + (xs1[k] + av1[k]);
    }
    if (j < m) {
        int2 p0 = __ldg(&sp[j]);
        float xs0[8], av0[8];
        ldg_xh8(g_xh + (size_t)p0.x * D_FEAT + c, xs0);
        ldg_ef8(ea   + (size_t)p0.y * D_FEAT + c, av0);
        #pragma unroll
        for (int k = 0; k < 8; ++k) acc[k] += xs0[k] + av0[k];
    }

    float dg = (float)deg;           // true degree (incl. overflow edges)
    float xv[8];                     // fp32-exact diagonal term
    ldg_el8(x + (size_t)node * D_FEAT + c, xv);
    float4 r0 = make_float4(acc[0] + dg * xv[0], acc[1] + dg * xv[1],
                            acc[2] + dg * xv[2], acc[3] + dg * xv[3]);
    float4 r1 = make_float4(acc[4] + dg * xv[4], acc[5] + dg * xv[5],
                            acc[6] + dg * xv[6], acc[7] + dg * xv[7]);
    float* op = out + (size_t)node * D_FEAT + c;
    __stcs(reinterpret_cast<float4*>(op), r0);
    __stcs(reinterpret_cast<float4*>(op + 4), r1);
}

// ---------------------------------------------------------------------------
// K3: overflow edges (normally zero) — exact fp32 red.v4 scatter-add.
// ---------------------------------------------------------------------------
__device__ __forceinline__ void red_add_v4(float* p, float4 v) {
    asm volatile("red.global.add.v4.f32 [%0], {%1, %2, %3, %4};"
                 :: "l"(p), "f"(v.x), "f"(v.y), "f"(v.z), "f"(v.w)
                 : "memory");
}
__global__ void ovf_kernel(const float* __restrict__ x,
                           const float* __restrict__ ea,
                           float* __restrict__ out, int N) {
    int n = g_cnt[N];
    if (n > OVF_CAP) n = OVF_CAP;
    for (int i = threadIdx.x; i < n; i += blockDim.x) {
        int3 v = g_ovf[i];
        #pragma unroll
        for (int c = 0; c < D_FEAT; c += 4) {
            float4 xs = __ldg(reinterpret_cast<const float4*>(
                x + (size_t)v.x * D_FEAT + c));
            float4 av = __ldg(reinterpret_cast<const float4*>(
                ea + (size_t)v.y * D_FEAT + c));
            red_add_v4(out + (size_t)v.z * D_FEAT + c,
                       make_float4(xs.x + av.x, xs.y + av.y,
                                   xs.z + av.z, xs.w + av.w));
        }
    }
}

// ---------------------------------------------------------------------------
// Fallback (unexpected shapes): zero out + red.v4 scatter of full message.
// ---------------------------------------------------------------------------
__global__ void zero_out_kernel(float4* out4, int n4) {
    int i = blockIdx.x * blockDim.x + threadIdx.x;
    if (i < n4) out4[i] = make_float4(0.f, 0.f, 0.f, 0.f);
}
__global__ void edge_full_kernel(const float* __restrict__ x,
                                 const float* __restrict__ ea,
                                 const void* __restrict__ idx,
                                 float* __restrict__ out, int E, int N) {
    int is64 = detect_is64(idx, E, N);
    long long gid = (long long)blockIdx.x * blockDim.x + threadIdx.x;
    long long e = gid >> 4;
    if (e >= E) return;
    int c = ((int)gid & 15) << 2;
    int s = load_idx(idx, e, is64);
    int d = load_idx(idx, (long long)E + e, is64);
    if ((unsigned)s >= (unsigned)N || (unsigned)d >= (unsigned)N) return;
    float4 xs = __ldg(reinterpret_cast<const float4*>(x + (size_t)s * D_FEAT + c));
    float4 xd = __ldg(reinterpret_cast<const float4*>(x + (size_t)d * D_FEAT + c));
    float4 av = __ldcs(reinterpret_cast<const float4*>(ea + (size_t)e * D_FEAT + c));
    float4 m = make_float4(xs.x + xd.x + av.x, xs.y + xd.y + av.y,
                           xs.z + xd.z + av.z, xs.w + xd.w + av.w);
    red_add_v4(out + (size_t)d * D_FEAT + c, m);
}

// ---------------------------------------------------------------------------
// Launcher: memset + cvt(x->fp16) + scatter + agg + ovf.
// Order-proof input identification; dtype detected per-block on device.
// ---------------------------------------------------------------------------
extern "C" void kernel_launch(void* const* d_in, const int* in_sizes, int n_in,
                              void* d_out, int out_size) {
    int xi = -1;
    for (int i = 0; i < n_in; ++i)
        if (in_sizes[i] == out_size) { xi = i; break; }
    int a = -1, b = -1;
    for (int i = 0; i < n_in; ++i) {
        if (i == xi) continue;
        if (a < 0) a = i; else b = i;
    }
    int ii = (in_sizes[a] < in_sizes[b]) ? a : b;
    int ei = (ii == a) ? b : a;

    const float* x   = (const float*)d_in[xi];
    const float* ea  = (const float*)d_in[ei];
    const void*  idx = d_in[ii];
    float* out = (float*)d_out;

    const int N = out_size / D_FEAT;     // 50000
    const int E = in_sizes[ii] / 2;      // 1250000

    if (N <= NMAX) {
        void* cntp = nullptr; cudaGetSymbolAddress(&cntp, g_cnt);
        cudaMemsetAsync(cntp, 0, (size_t)(N + 1) * sizeof(int), 0);

        int n8 = N * (D_FEAT / 8);       // 400K convert threads
        cvt_kernel<<<(n8 + 255) / 256, 256>>>(x, n8);

        int eThreads = (E + 3) / 4;
        scatter_kernel<<<(eThreads + 255) / 256, 256>>>(idx, E, N);
        long long th = (long long)N * 8;
        agg_kernel<<<(int)((th + 127) / 128), 128>>>(x, ea, out, N);
        ovf_kernel<<<1, 256>>>(x, ea, out, N);
    } else {
        int n4 = out_size / 4;
        zero_out_kernel<<<(n4 + 255) / 256, 256>>>((float4*)out, n4);
        long long total = (long long)E * 16;
        edge_full_kernel<<<(int)((total + 255) / 256), 256>>>(x, ea, idx, out, E, N);
    }
}

// round 17
// speedup vs baseline: 1.2131x; 1.2131x over previous
#include <cuda_runtime.h>
#include <cstdint>

// Dataset: N=50000 nodes, E=1250000 edges, D=64.
#define D_FEAT   64
#define NMAX     65536
#define SLOTS    96            // bucket capacity per node (Poisson(25): P(>96)~1e-30)
#define OVF_CAP  65536

// g_cnt[0..N-1] = per-node edge count; g_cnt[N] = overflow counter.
// One contiguous memset clears both.
__device__ int  g_cnt[NMAX + 1];
__device__ int2 g_slot[(size_t)NMAX * SLOTS];      // (src, eid) buckets, stride 96
__device__ int3 g_ovf[OVF_CAP];                    // (src, eid, dst) overflow edges

__device__ __forceinline__ int load_idx(const void* idx, long long i, int is64) {
    if (is64) return (int)((const long long*)idx)[i];
    return ((const int*)idx)[i];
}

// Per-block dtype detection (int32 misread as int64 lands in [0,N) w.p. ~2e-5/sample)
__device__ __forceinline__ int detect_is64(const void* idx, int E, int N) {
    __shared__ int s_is64;
    if (threadIdx.x < 32) {
        int step = E / 32 > 0 ? E / 32 : 1;
        long long v = ((const long long*)idx)[(long long)threadIdx.x * step];
        bool okv = (v >= 0 && v < (long long)N);
        unsigned m = __ballot_sync(0xFFFFFFFFu, okv);
        if (threadIdx.x == 0) s_is64 = (m == 0xFFFFFFFFu) ? 1 : 0;
    }
    __syncthreads();
    return s_is64;
}

// 256-bit loads with L2 eviction priority (sm_103: evict hints need .v8.b32).
__device__ __forceinline__ void ldg_el8(const float* p, float* o) {
    unsigned r0, r1, r2, r3, r4, r5, r6, r7;
    asm volatile("ld.global.nc.L2::evict_last.v8.b32 {%0,%1,%2,%3,%4,%5,%6,%7}, [%8];"
                 : "=r"(r0), "=r"(r1), "=r"(r2), "=r"(r3),
                   "=r"(r4), "=r"(r5), "=r"(r6), "=r"(r7) : "l"(p));
    o[0] = __uint_as_float(r0); o[1] = __uint_as_float(r1);
    o[2] = __uint_as_float(r2); o[3] = __uint_as_float(r3);
    o[4] = __uint_as_float(r4); o[5] = __uint_as_float(r5);
    o[6] = __uint_as_float(r6); o[7] = __uint_as_float(r7);
}
__device__ __forceinline__ void ldg_ef8(const float* p, float* o) {
    unsigned r0, r1, r2, r3, r4, r5, r6, r7;
    asm volatile("ld.global.nc.L2::evict_first.v8.b32 {%0,%1,%2,%3,%4,%5,%6,%7}, [%8];"
                 : "=r"(r0), "=r"(r1), "=r"(r2), "=r"(r3),
                   "=r"(r4), "=r"(r5), "=r"(r6), "=r"(r7) : "l"(p));
    o[0] = __uint_as_float(r0); o[1] = __uint_as_float(r1);
    o[2] = __uint_as_float(r2); o[3] = __uint_as_float(r3);
    o[4] = __uint_as_float(r4); o[5] = __uint_as_float(r5);
    o[6] = __uint_as_float(r6); o[7] = __uint_as_float(r7);
}

// ---------------------------------------------------------------------------
// K1: scatter — 4 edges/thread (E/4 threads = exactly one full chip wave),
// vectorized index loads. At the LSU/LTS transaction floor for 1.25M
// divergent atomic+store pairs (~25us, invariant across all variants tried).
// Counter doubles as degree; no histogram, no scan.
// ---------------------------------------------------------------------------
__global__ void scatter_kernel(const void* __restrict__ idx, int E, int N) {
    int is64 = detect_is64(idx, E, N);
    int base = (blockIdx.x * blockDim.x + threadIdx.x) * 4;
    if (base >= E) return;
    int s[4], d[4];

    if (base + 4 <= E) {
        if (is64) {
            const longlong2* ps = reinterpret_cast<const longlong2*>(
                (const long long*)idx + base);
            const longlong2* pd = reinterpret_cast<const longlong2*>(
                (const long long*)idx + E + base);
            longlong2 s01 = __ldg(ps), s23 = __ldg(ps + 1);
            longlong2 d01 = __ldg(pd), d23 = __ldg(pd + 1);
            s[0] = (int)s01.x; s[1] = (int)s01.y; s[2] = (int)s23.x; s[3] = (int)s23.y;
            d[0] = (int)d01.x; d[1] = (int)d01.y; d[2] = (int)d23.x; d[3] = (int)d23.y;
        } else {
            int4 sv = __ldg(reinterpret_cast<const int4*>((const int*)idx + base));
            int4 dv = __ldg(reinterpret_cast<const int4*>((const int*)idx + E + base));
            s[0] = sv.x; s[1] = sv.y; s[2] = sv.z; s[3] = sv.w;
            d[0] = dv.x; d[1] = dv.y; d[2] = dv.z; d[3] = dv.w;
        }
    } else {
        #pragma unroll
        for (int k = 0; k < 4; ++k) {
            if (base + k < E) {
                s[k] = load_idx(idx, base + k, is64);
                d[k] = load_idx(idx, (long long)E + base + k, is64);
            } else { s[k] = -1; d[k] = -1; }
        }
    }

    #pragma unroll
    for (int k = 0; k < 4; ++k) {
        if ((unsigned)s[k] < (unsigned)N && (unsigned)d[k] < (unsigned)N) {
            int pos = atomicAdd(&g_cnt[d[k]], 1);
            if (pos < SLOTS) {
                g_slot[(size_t)d[k] * SLOTS + pos] = make_int2(s[k], base + k);
            } else {
                int o = atomicAdd(&g_cnt[N], 1);     // overflow counter
                if (o < OVF_CAP) g_ovf[o] = make_int3(s[k], base + k, d[k]);
            }
        }
    }
}

// ---------------------------------------------------------------------------
// K2: aggregation — static one node per 8-lane group, T=128 (16 nodes/CTA:
// finer CTA granularity absorbs the Poisson-degree tail better than 32).
// 32B lane chunks, unroll-2, x pinned in L2 (evict_last), ea streamed
// (evict_first), out stored streaming (__stcs). At the L2/LSU gather
// request-rate wall (fp16-traffic-halving experiment proved byte-BW is not
// the binding resource).
// out[n] = deg(n)*x[n] + sum_{e: dst=n} (x[src_e] + ea[e])
// ---------------------------------------------------------------------------
__global__ void __launch_bounds__(128) agg_kernel(const float* __restrict__ x,
                                                  const float* __restrict__ ea,
                                                  float* __restrict__ out, int N) {
    int t = blockIdx.x * blockDim.x + threadIdx.x;
    int node = t >> 3;               // one node per 8-lane group
    if (node >= N) return;
    int c = (t & 7) << 3;            // float column offset: 0,8,...,56

    int deg = g_cnt[node];
    int m = deg < SLOTS ? deg : SLOTS;
    const int2* __restrict__ sp = g_slot + (size_t)node * SLOTS;

    float acc[8] = {0.f, 0.f, 0.f, 0.f, 0.f, 0.f, 0.f, 0.f};
    int j = 0;
    for (; j + 1 < m; j += 2) {
        int2 p0 = __ldg(&sp[j]);
        int2 p1 = __ldg(&sp[j + 1]);
        float xs0[8], av0[8], xs1[8], av1[8];
        ldg_el8(x  + (size_t)p0.x * D_FEAT + c, xs0);
        ldg_ef8(ea + (size_t)p0.y * D_FEAT + c, av0);
        ldg_el8(x  + (size_t)p1.x * D_FEAT + c, xs1);
        ldg_ef8(ea + (size_t)p1.y * D_FEAT + c, av1);
        #pragma unroll
        for (int k = 0; k < 8; ++k)
            acc[k] += (xs0[k] + av0[k]) + (xs1[k] + av1[k]);
    }
    if (j < m) {
        int2 p0 = __ldg(&sp[j]);
        float xs0[8], av0[8];
        ldg_el8(x  + (size_t)p0.x * D_FEAT + c, xs0);
        ldg_ef8(ea + (size_t)p0.y * D_FEAT + c, av0);
        #pragma unroll
        for (int k = 0; k < 8; ++k) acc[k] += xs0[k] + av0[k];
    }

    float dg = (float)deg;           // true degree (incl. overflow edges)
    float xv[8];
    ldg_el8(x + (size_t)node * D_FEAT + c, xv);
    float4 r0 = make_float4(acc[0] + dg * xv[0], acc[1] + dg * xv[1],
                            acc[2] + dg * xv[2], acc[3] + dg * xv[3]);
    float4 r1 = make_float4(acc[4] + dg * xv[4], acc[5] + dg * xv[5],
                            acc[6] + dg * xv[6], acc[7] + dg * xv[7]);
    float* op = out + (size_t)node * D_FEAT + c;
    __stcs(reinterpret_cast<float4*>(op), r0);
    __stcs(reinterpret_cast<float4*>(op + 4), r1);
}

// ---------------------------------------------------------------------------
// K3: overflow edges (normally zero) — exact red.v4 scatter-add into out.
// ---------------------------------------------------------------------------
__device__ __forceinline__ void red_add_v4(float* p, float4 v) {
    asm volatile("red.global.add.v4.f32 [%0], {%1, %2, %3, %4};"
                 :: "l"(p), "f"(v.x), "f"(v.y), "f"(v.z), "f"(v.w)
                 : "memory");
}
__global__ void ovf_kernel(const float* __restrict__ x,
                           const float* __restrict__ ea,
                           float* __restrict__ out, int N) {
    int n = g_cnt[N];
    if (n > OVF_CAP) n = OVF_CAP;
    for (int i = threadIdx.x; i < n; i += blockDim.x) {
        int3 v = g_ovf[i];
        #pragma unroll
        for (int c = 0; c < D_FEAT; c += 4) {
            float4 xs = __ldg(reinterpret_cast<const float4*>(
                x + (size_t)v.x * D_FEAT + c));
            float4 av = __ldg(reinterpret_cast<const float4*>(
                ea + (size_t)v.y * D_FEAT + c));
            red_add_v4(out + (size_t)v.z * D_FEAT + c,
                       make_float4(xs.x + av.x, xs.y + av.y,
                                   xs.z + av.z, xs.w + av.w));
        }
    }
}

// ---------------------------------------------------------------------------
// Fallback (unexpected shapes): zero out + red.v4 scatter of full message.
// ---------------------------------------------------------------------------
__global__ void zero_out_kernel(float4* out4, int n4) {
    int i = blockIdx.x * blockDim.x + threadIdx.x;
    if (i < n4) out4[i] = make_float4(0.f, 0.f, 0.f, 0.f);
}
__global__ void edge_full_kernel(const float* __restrict__ x,
                                 const float* __restrict__ ea,
                                 const void* __restrict__ idx,
                                 float* __restrict__ out, int E, int N) {
    int is64 = detect_is64(idx, E, N);
    long long gid = (long long)blockIdx.x * blockDim.x + threadIdx.x;
    long long e = gid >> 4;
    if (e >= E) return;
    int c = ((int)gid & 15) << 2;
    int s = load_idx(idx, e, is64);
    int d = load_idx(idx, (long long)E + e, is64);
    if ((unsigned)s >= (unsigned)N || (unsigned)d >= (unsigned)N) return;
    float4 xs = __ldg(reinterpret_cast<const float4*>(x + (size_t)s * D_FEAT + c));
    float4 xd = __ldg(reinterpret_cast<const float4*>(x + (size_t)d * D_FEAT + c));
    float4 av = __ldcs(reinterpret_cast<const float4*>(ea + (size_t)e * D_FEAT + c));
    float4 m = make_float4(xs.x + xd.x + av.x, xs.y + xd.y + av.y,
                           xs.z + xd.z + av.z, xs.w + xd.w + av.w);
    red_add_v4(out + (size_t)d * D_FEAT + c, m);
}

// ---------------------------------------------------------------------------
// Launcher: ONE memset (cnt + ovf counter contiguous) + scatter + agg + ovf.
// Order-proof input identification; dtype detected per-block on device.
// ---------------------------------------------------------------------------
extern "C" void kernel_launch(void* const* d_in, const int* in_sizes, int n_in,
                              void* d_out, int out_size) {
    int xi = -1;
    for (int i = 0; i < n_in; ++i)
        if (in_sizes[i] == out_size) { xi = i; break; }
    int a = -1, b = -1;
    for (int i = 0; i < n_in; ++i) {
        if (i == xi) continue;
        if (a < 0) a = i; else b = i;
    }
    int ii = (in_sizes[a] < in_sizes[b]) ? a : b;
    int ei = (ii == a) ? b : a;

    const float* x   = (const float*)d_in[xi];
    const float* ea  = (const float*)d_in[ei];
    const void*  idx = d_in[ii];
    float* out = (float*)d_out;

    const int N = out_size / D_FEAT;     // 50000
    const int E = in_sizes[ii] / 2;      // 1250000

    if (N <= NMAX) {
        void* cntp = nullptr; cudaGetSymbolAddress(&cntp, g_cnt);
        cudaMemsetAsync(cntp, 0, (size_t)(N + 1) * sizeof(int), 0);

        int eThreads = (E + 3) / 4;
        scatter_kernel<<<(eThreads + 255) / 256, 256>>>(idx, E, N);
        long long th = (long long)N * 8;
        agg_kernel<<<(int)((th + 127) / 128), 128>>>(x, ea, out, N);
        ovf_kernel<<<1, 256>>>(x, ea, out, N);
    } else {
        int n4 = out_size / 4;
        zero_out_kernel<<<(n4 + 255) / 256, 256>>>((float4*)out, n4);
        long long total = (long long)E * 16;
        edge_full_kernel<<<(int)((total + 255) / 256), 256>>>(x, ea, idx, out, E, N);
    }
}